// round 4
// baseline (speedup 1.0000x reference)
#include <cuda_runtime.h>
#include <cuda_bf16.h>

#define NN 10000
#define EE 160000

// ---------------- scratch (device globals: allocation-free) ----------------
// g_u   : [n][c][4] = {u0, u1_x, u1_y, u1_z}          (20.5 MB)
// g_down: [n][64]                                      (2.6 MB)
// g_m   : [n][256][4] = {m0, m1_x, m1_y, m1_z}         (41 MB, zeroed per launch)
__device__ float g_u[NN * 128 * 4];
__device__ float g_down[NN * 64];
__device__ float g_m[NN * 256 * 4];

// scale constants
#define INV_S128 0.08838834764831845f   // 1/sqrt(128)
#define INV_S136 0.08574929257125442f   // 1/sqrt(136)
#define INV_S256 0.0625f                // 1/sqrt(256)
#define INV_SQRT3 0.5773502691896258f
#define FINAL_SCALE 0.00390625f         // (1/sqrt(256)) / 16

// ---------------- packed f32x2 helpers (sm_100+ FFMA2 pipe) -----------------
__device__ __forceinline__ unsigned long long bcast2(float x) {
    unsigned long long r;
    asm("mov.b64 %0, {%1, %1};" : "=l"(r) : "f"(x));
    return r;
}
__device__ __forceinline__ void fma2(unsigned long long& d,
                                     unsigned long long a, unsigned long long b) {
    asm("fma.rn.f32x2 %0, %1, %2, %0;" : "+l"(d) : "l"(a), "l"(b));
}
__device__ __forceinline__ void unpack2(unsigned long long v, float& lo, float& hi) {
    asm("mov.b64 {%0, %1}, %2;" : "=f"(lo), "=f"(hi) : "l"(v));
}

// ---------------------------------------------------------------------------
// Kernel 0: zero the accumulator buffer
// ---------------------------------------------------------------------------
__global__ void zero_m_kernel() {
    int i = blockIdx.x * blockDim.x + threadIdx.x;       // one float4 each
    if (i < NN * 256) ((float4*)g_m)[i] = make_float4(0.f, 0.f, 0.f, 0.f);
}

// ---------------------------------------------------------------------------
// Kernel 1: node transforms. 8 nodes per block, 256 threads.
// Computes sc (written to out), u0/u1 (-> g_u), down (-> g_down).
// ---------------------------------------------------------------------------
#define K1_SMEM ((8 * 520 + 4 * 32 * 128 + 32 * 64) * 4)

__global__ __launch_bounds__(256, 1) void node_kernel(
    const float* __restrict__ nf,
    const float* __restrict__ Ws0, const float* __restrict__ Ws1,
    const float* __restrict__ Wu0, const float* __restrict__ Wu1,
    const float* __restrict__ Wd,
    float* __restrict__ out_sc)
{
    extern __shared__ float sm[];
    float* sX   = sm;                 // 8 rows x 520 (512 used)
    float* sWs0 = sX + 8 * 520;       // 32 x 128
    float* sWu0 = sWs0 + 32 * 128;
    float* sWs1 = sWu0 + 32 * 128;
    float* sWu1 = sWs1 + 32 * 128;
    float* sWd  = sWu1 + 32 * 128;    // 32 x 64

    const int tid = threadIdx.x;
    const int n0 = blockIdx.x * 8;

    for (int g = tid; g < 8 * 128; g += 256) {
        int nn = g >> 7, q = g & 127;
        ((float4*)(sX + nn * 520))[q] = ((const float4*)nf)[(size_t)(n0 + nn) * 128 + q];
    }

    const int v = tid & 127, grp = tid >> 7;
    float a_sc0[4] = {0,0,0,0}, a_u0[4] = {0,0,0,0}, a_dn[4] = {0,0,0,0};
    float a_sc1[4][3] = {{0}}, a_u1[4][3] = {{0}};

    for (int k0 = 0; k0 < 128; k0 += 32) {
        __syncthreads();
        for (int g = tid; g < 32 * 128; g += 256) {
            int r = g >> 7, c = g & 127;
            sWs0[g] = Ws0[(k0 + r) * 128 + c];
            sWu0[g] = Wu0[(k0 + r) * 128 + c];
            sWs1[g] = Ws1[(k0 + r) * 128 + c];
            sWu1[g] = Wu1[(k0 + r) * 128 + c];
        }
        for (int g = tid; g < 32 * 64; g += 256) {
            int r = g >> 6, c = g & 63;
            sWd[g] = Wd[(k0 + r) * 64 + c];
        }
        __syncthreads();
#pragma unroll 4
        for (int uu = 0; uu < 32; uu++) {
            const int u = k0 + uu;
            const float ws0 = sWs0[uu * 128 + v];
            const float wu0 = sWu0[uu * 128 + v];
            const float ws1 = sWs1[uu * 128 + v];
            const float wu1 = sWu1[uu * 128 + v];
            const float wd  = (v < 64) ? sWd[uu * 64 + v] : 0.f;
#pragma unroll
            for (int nn = 0; nn < 4; nn++) {
                const float* xr = sX + (grp * 4 + nn) * 520;
                const float a0 = xr[u];
                const float b0 = xr[128 + u * 3 + 0];
                const float b1 = xr[128 + u * 3 + 1];
                const float b2 = xr[128 + u * 3 + 2];
                a_sc0[nn] = fmaf(a0, ws0, a_sc0[nn]);
                a_u0[nn]  = fmaf(a0, wu0, a_u0[nn]);
                a_dn[nn]  = fmaf(a0, wd,  a_dn[nn]);
                a_sc1[nn][0] = fmaf(b0, ws1, a_sc1[nn][0]);
                a_sc1[nn][1] = fmaf(b1, ws1, a_sc1[nn][1]);
                a_sc1[nn][2] = fmaf(b2, ws1, a_sc1[nn][2]);
                a_u1[nn][0] = fmaf(b0, wu1, a_u1[nn][0]);
                a_u1[nn][1] = fmaf(b1, wu1, a_u1[nn][1]);
                a_u1[nn][2] = fmaf(b2, wu1, a_u1[nn][2]);
            }
        }
    }

#pragma unroll
    for (int nn = 0; nn < 4; nn++) {
        const int n = n0 + grp * 4 + nn;
        out_sc[(size_t)n * 512 + v] = a_sc0[nn] * INV_S128;
        out_sc[(size_t)n * 512 + 128 + v * 3 + 0] = a_sc1[nn][0] * INV_S128;
        out_sc[(size_t)n * 512 + 128 + v * 3 + 1] = a_sc1[nn][1] * INV_S128;
        out_sc[(size_t)n * 512 + 128 + v * 3 + 2] = a_sc1[nn][2] * INV_S128;
        float4 uo = make_float4(a_u0[nn] * INV_S128, a_u1[nn][0] * INV_S128,
                                a_u1[nn][1] * INV_S128, a_u1[nn][2] * INV_S128);
        *(float4*)(&g_u[((size_t)n * 128 + v) * 4]) = uo;
        if (v < 64) g_down[(size_t)n * 64 + v] = a_dn[nn] * INV_S128;
    }
}

// ---------------------------------------------------------------------------
// Kernel 2: fused edge MLP + message scatter. 64 edges / block, 256 threads.
// ---------------------------------------------------------------------------
#define TE 64
#define LDA 260
#define KC 16                                   // k-chunk
#define K2_SMEM ((TE * LDA * 2 + KC * LDA + 256 + 128) * 4)

__device__ __forceinline__ void red4(float* p, float4 v) {
    asm volatile("red.global.add.v4.f32 [%0], {%1, %2, %3, %4};"
                 :: "l"(p), "f"(v.x), "f"(v.y), "f"(v.z), "f"(v.w) : "memory");
}

// block GEMM: out[64,256] = silu?( scale * in[64,Kreal] @ W[Kreal, col0:col0+256] )
// Kpad multiple of KC; padded weight rows zeroed here, padded input columns
// zeroed by the caller. Inner product uses packed fma.rn.f32x2 (FFMA2).
__device__ __forceinline__ void mlp_layer(
    const float* __restrict__ Wg, int ldw, int col0, int Kreal, int Kpad,
    const float* sIn, float* sOut, float* sWst,
    float scale, bool act)
{
    const int tid = threadIdx.x;
    const int tx = tid & 31, ty = tid >> 5;
    unsigned long long acc2[8][4];              // 8 rows x 4 f32x2 pairs = 8x8 floats
#pragma unroll
    for (int i = 0; i < 8; i++)
#pragma unroll
        for (int j = 0; j < 4; j++) acc2[i][j] = 0ull;

    for (int k0 = 0; k0 < Kpad; k0 += KC) {
        __syncthreads();
#pragma unroll
        for (int r = 0; r < KC; r++) {
            const int krow = k0 + r;
            sWst[r * LDA + tid] = (krow < Kreal) ? Wg[(size_t)krow * ldw + col0 + tid] : 0.f;
        }
        __syncthreads();
#pragma unroll
        for (int kk = 0; kk < KC; kk++) {
            unsigned long long a2[8];
#pragma unroll
            for (int i = 0; i < 8; i++)
                a2[i] = bcast2(sIn[(ty * 8 + i) * LDA + k0 + kk]);
            // 8 adjacent weights -> 4 x 64-bit shared loads (16B-aligned pairs)
            const unsigned long long* wp =
                (const unsigned long long*)(sWst + kk * LDA + tx * 8);
            const unsigned long long w0 = wp[0], w1 = wp[1], w2 = wp[2], w3 = wp[3];
#pragma unroll
            for (int i = 0; i < 8; i++) {
                fma2(acc2[i][0], a2[i], w0);
                fma2(acc2[i][1], a2[i], w1);
                fma2(acc2[i][2], a2[i], w2);
                fma2(acc2[i][3], a2[i], w3);
            }
        }
    }
    __syncthreads();
#pragma unroll
    for (int i = 0; i < 8; i++) {
        float v[8];
#pragma unroll
        for (int j = 0; j < 4; j++) unpack2(acc2[i][j], v[2 * j], v[2 * j + 1]);
#pragma unroll
        for (int j = 0; j < 8; j++) {
            float x = v[j] * scale;
            if (act) x = x * (1.0f / (1.0f + __expf(-x)));
            v[j] = x;
        }
        *(float4*)(sOut + (ty * 8 + i) * LDA + tx * 8)     = make_float4(v[0], v[1], v[2], v[3]);
        *(float4*)(sOut + (ty * 8 + i) * LDA + tx * 8 + 4) = make_float4(v[4], v[5], v[6], v[7]);
    }
    __syncthreads();
}

__device__ __forceinline__ void scatter_half(
    const float* sTP, const int* sSend, const int* sRecv, const float* sEA, int half)
{
    const int tid = threadIdx.x;
    for (int g = tid; g < TE * 128; g += 256) {
        const int e = g >> 7, c = g & 127;
        const int s = sSend[e], r = sRecv[e];
        const float4 ea = *(const float4*)(sEA + e * 4);   // y0 = ea.x, y1 = ea.y/z/w
        const float4 u = *(const float4*)(&g_u[((size_t)s * 128 + c) * 4]);
        const float* tp = sTP + e * LDA;
        float4 out;
        if (half == 0) {
            const float w0 = tp[c], w1 = tp[128 + c];
            const float t0 = w0 * u.x;      // o0a
            const float t1 = w1 * u.x;      // o1a base
            out.x = t0 * ea.x;
            out.y = t1 * ea.y; out.z = t1 * ea.z; out.w = t1 * ea.w;
            red4(&g_m[((size_t)r * 256 + c) * 4], out);
        } else {
            const float w2 = tp[c], w3 = tp[128 + c];
            const float dot = u.y * ea.y + u.z * ea.z + u.w * ea.w;
            out.x = w3 * dot * INV_SQRT3;   // o0b
            out.y = w2 * u.y * ea.x;        // o1b
            out.z = w2 * u.z * ea.x;
            out.w = w2 * u.w * ea.x;
            red4(&g_m[((size_t)r * 256 + 128 + c) * 4], out);
        }
    }
}

__global__ __launch_bounds__(256, 1) void edge_kernel(
    const float* __restrict__ ef, const float* __restrict__ ea,
    const int* __restrict__ eidx,
    const float* __restrict__ w1, const float* __restrict__ w2,
    const float* __restrict__ w3, const float* __restrict__ w4)
{
    extern __shared__ float sm[];
    float* sA  = sm;                       // 64 x 260
    float* sB  = sA + TE * LDA;            // 64 x 260
    float* sW  = sB + TE * LDA;            // KC x 260
    float* sEA = sW + KC * LDA;            // 64 x 4 (16B aligned)
    int*  sSend = (int*)(sEA + 256);       // 64
    int*  sRecv = sSend + 64;              // 64

    const int tid = threadIdx.x;
    const int e0 = blockIdx.x * TE;

    if (tid < TE) {
        sSend[tid] = eidx[e0 + tid];
        sRecv[tid] = eidx[EE + e0 + tid];
    }
    sEA[tid] = ea[(size_t)e0 * 4 + tid];   // 256 values
    __syncthreads();

    // build aug = [edge_feats(8) | down[s](64) | down[r](64) | zero-pad(8)]
    for (int g = tid; g < TE * 8; g += 256) {
        int e = g >> 3, j = g & 7;
        sA[e * LDA + j] = ef[(size_t)(e0 + e) * 8 + j];
        sA[e * LDA + 136 + j] = 0.f;       // pad cols 136..143 (NaN guard)
    }
    for (int g = tid; g < TE * 64; g += 256) {
        int e = g >> 6, j = g & 63;
        sA[e * LDA + 8 + j]  = g_down[(size_t)sSend[e] * 64 + j];
        sA[e * LDA + 72 + j] = g_down[(size_t)sRecv[e] * 64 + j];
    }
    __syncthreads();

    mlp_layer(w1, 256, 0,   136, 144, sA, sB, sW, INV_S136, true);
    mlp_layer(w2, 256, 0,   256, 256, sB, sA, sW, INV_S256, true);
    mlp_layer(w3, 256, 0,   256, 256, sA, sB, sW, INV_S256, true);
    mlp_layer(w4, 512, 0,   256, 256, sB, sA, sW, INV_S256, false);  // {w0,w1}
    scatter_half(sA, sSend, sRecv, sEA, 0);
    __syncthreads();
    mlp_layer(w4, 512, 256, 256, 256, sB, sA, sW, INV_S256, false);  // {w2,w3}
    scatter_half(sA, sSend, sRecv, sEA, 1);
}

// ---------------------------------------------------------------------------
// Kernel 3: final node GEMM -> message output. 8 nodes / block, 256 threads.
// ---------------------------------------------------------------------------
#define K3_SMEM ((8 * 1024 + 2 * 32 * 128) * 4)

__global__ __launch_bounds__(256, 1) void final_kernel(
    const float* __restrict__ Wl0, const float* __restrict__ Wl1,
    float* __restrict__ out_msg)
{
    extern __shared__ float sm[];
    float* sM  = sm;                  // 8 x 1024 (= 256 float4 rows)
    float* sL0 = sM + 8 * 1024;       // 32 x 128
    float* sL1 = sL0 + 32 * 128;

    const int tid = threadIdx.x;
    const int n0 = blockIdx.x * 8;

    for (int g = tid; g < 8 * 256; g += 256) {
        int nn = g >> 8, q = g & 255;
        ((float4*)(sM + nn * 1024))[q] = ((const float4*)g_m)[(size_t)(n0 + nn) * 256 + q];
    }

    const int v = tid & 127, grp = tid >> 7;
    float acc0[4] = {0,0,0,0};
    float acc1[4][3] = {{0}};

    for (int k0 = 0; k0 < 256; k0 += 32) {
        __syncthreads();
        for (int g = tid; g < 32 * 128; g += 256) {
            int r = g >> 7, c = g & 127;
            sL0[g] = Wl0[(k0 + r) * 128 + c];
            sL1[g] = Wl1[(k0 + r) * 128 + c];
        }
        __syncthreads();
#pragma unroll 4
        for (int uu = 0; uu < 32; uu++) {
            const float w0 = sL0[uu * 128 + v];
            const float w1 = sL1[uu * 128 + v];
#pragma unroll
            for (int nn = 0; nn < 4; nn++) {
                const float4 a = *(const float4*)(sM + (grp * 4 + nn) * 1024 + (k0 + uu) * 4);
                acc0[nn]    = fmaf(a.x, w0, acc0[nn]);
                acc1[nn][0] = fmaf(a.y, w1, acc1[nn][0]);
                acc1[nn][1] = fmaf(a.z, w1, acc1[nn][1]);
                acc1[nn][2] = fmaf(a.w, w1, acc1[nn][2]);
            }
        }
    }

#pragma unroll
    for (int nn = 0; nn < 4; nn++) {
        const int n = n0 + grp * 4 + nn;
        float4 o = make_float4(acc0[nn] * FINAL_SCALE, acc1[nn][0] * FINAL_SCALE,
                               acc1[nn][1] * FINAL_SCALE, acc1[nn][2] * FINAL_SCALE);
        *(float4*)(out_msg + (size_t)n * 512 + v * 4) = o;
    }
}

// ---------------------------------------------------------------------------
extern "C" void kernel_launch(void* const* d_in, const int* in_sizes, int n_in,
                              void* d_out, int out_size)
{
    const float* node_feats = (const float*)d_in[1];
    const float* edge_attrs = (const float*)d_in[2];
    const float* edge_feats = (const float*)d_in[3];
    const int*   edge_index = (const int*)d_in[4];
    const float* W_up0   = (const float*)d_in[5];
    const float* W_up1   = (const float*)d_in[6];
    const float* W_down  = (const float*)d_in[7];
    const float* mlp_w1  = (const float*)d_in[8];
    const float* mlp_w2  = (const float*)d_in[9];
    const float* mlp_w3  = (const float*)d_in[10];
    const float* mlp_w4  = (const float*)d_in[11];
    const float* W_lin0  = (const float*)d_in[12];
    const float* W_lin1  = (const float*)d_in[13];
    const float* W_skip0 = (const float*)d_in[14];
    const float* W_skip1 = (const float*)d_in[15];
    float* out = (float*)d_out;   // [message (N*512) | sc (N*512)]

    cudaFuncSetAttribute(node_kernel,  cudaFuncAttributeMaxDynamicSharedMemorySize, K1_SMEM);
    cudaFuncSetAttribute(edge_kernel,  cudaFuncAttributeMaxDynamicSharedMemorySize, K2_SMEM);
    cudaFuncSetAttribute(final_kernel, cudaFuncAttributeMaxDynamicSharedMemorySize, K3_SMEM);

    zero_m_kernel<<<NN, 256>>>();
    node_kernel<<<NN / 8, 256, K1_SMEM>>>(node_feats, W_skip0, W_skip1,
                                          W_up0, W_up1, W_down,
                                          out + (size_t)NN * 512);
    edge_kernel<<<EE / TE, 256, K2_SMEM>>>(edge_feats, edge_attrs, edge_index,
                                           mlp_w1, mlp_w2, mlp_w3, mlp_w4);
    final_kernel<<<NN / 8, 256, K3_SMEM>>>(W_lin0, W_lin1, out);
}

// round 13
// speedup vs baseline: 1.5761x; 1.5761x over previous
#include <cuda_runtime.h>
#include <cuda_bf16.h>

#define NN 10000
#define EE 160000

// ---------------- scratch (device globals: allocation-free) ----------------
__device__ float g_u[NN * 128 * 4];      // [n][c][4] = {u0, u1_x, u1_y, u1_z}
__device__ float g_down[NN * 64];        // [n][64]
__device__ float g_m[NN * 256 * 4];      // [n][256][4] accumulators

#define INV_S128 0.08838834764831845f   // 1/sqrt(128)
#define INV_S136 0.08574929257125442f   // 1/sqrt(136)
#define INV_S256 0.0625f                // 1/sqrt(256)
#define INV_SQRT3 0.5773502691896258f
#define FINAL_SCALE 0.00390625f         // (1/sqrt(256)) / 16

// ---------------- tf32 helpers ----------------
__device__ __forceinline__ unsigned f2tf32(float x) {
    unsigned r;
    asm("cvt.rna.tf32.f32 %0, %1;" : "=r"(r) : "f"(x));
    return r;
}
__device__ __forceinline__ void mma_tf32(float c[4], const unsigned a[4], const unsigned b[2]) {
    asm volatile(
        "mma.sync.aligned.m16n8k8.row.col.f32.tf32.tf32.f32 "
        "{%0,%1,%2,%3}, {%4,%5,%6,%7}, {%8,%9}, {%0,%1,%2,%3};"
        : "+f"(c[0]), "+f"(c[1]), "+f"(c[2]), "+f"(c[3])
        : "r"(a[0]), "r"(a[1]), "r"(a[2]), "r"(a[3]), "r"(b[0]), "r"(b[1]));
}

// ---------------------------------------------------------------------------
// Kernel 0: zero the accumulator buffer
// ---------------------------------------------------------------------------
__global__ void zero_m_kernel() {
    int i = blockIdx.x * blockDim.x + threadIdx.x;
    if (i < NN * 256) ((float4*)g_m)[i] = make_float4(0.f, 0.f, 0.f, 0.f);
}

// ---------------------------------------------------------------------------
// Kernel 1: node transforms (unchanged from passing R4 version).
// ---------------------------------------------------------------------------
#define K1_SMEM ((8 * 520 + 4 * 32 * 128 + 32 * 64) * 4)

__global__ __launch_bounds__(256, 1) void node_kernel(
    const float* __restrict__ nf,
    const float* __restrict__ Ws0, const float* __restrict__ Ws1,
    const float* __restrict__ Wu0, const float* __restrict__ Wu1,
    const float* __restrict__ Wd,
    float* __restrict__ out_sc)
{
    extern __shared__ float sm[];
    float* sX   = sm;                 // 8 rows x 520 (512 used)
    float* sWs0 = sX + 8 * 520;
    float* sWu0 = sWs0 + 32 * 128;
    float* sWs1 = sWu0 + 32 * 128;
    float* sWu1 = sWs1 + 32 * 128;
    float* sWd  = sWu1 + 32 * 128;

    const int tid = threadIdx.x;
    const int n0 = blockIdx.x * 8;

    for (int g = tid; g < 8 * 128; g += 256) {
        int nn = g >> 7, q = g & 127;
        ((float4*)(sX + nn * 520))[q] = ((const float4*)nf)[(size_t)(n0 + nn) * 128 + q];
    }

    const int v = tid & 127, grp = tid >> 7;
    float a_sc0[4] = {0,0,0,0}, a_u0[4] = {0,0,0,0}, a_dn[4] = {0,0,0,0};
    float a_sc1[4][3] = {{0}}, a_u1[4][3] = {{0}};

    for (int k0 = 0; k0 < 128; k0 += 32) {
        __syncthreads();
        for (int g = tid; g < 32 * 128; g += 256) {
            int r = g >> 7, c = g & 127;
            sWs0[g] = Ws0[(k0 + r) * 128 + c];
            sWu0[g] = Wu0[(k0 + r) * 128 + c];
            sWs1[g] = Ws1[(k0 + r) * 128 + c];
            sWu1[g] = Wu1[(k0 + r) * 128 + c];
        }
        for (int g = tid; g < 32 * 64; g += 256) {
            int r = g >> 6, c = g & 63;
            sWd[g] = Wd[(k0 + r) * 64 + c];
        }
        __syncthreads();
#pragma unroll 4
        for (int uu = 0; uu < 32; uu++) {
            const int u = k0 + uu;
            const float ws0 = sWs0[uu * 128 + v];
            const float wu0 = sWu0[uu * 128 + v];
            const float ws1 = sWs1[uu * 128 + v];
            const float wu1 = sWu1[uu * 128 + v];
            const float wd  = (v < 64) ? sWd[uu * 64 + v] : 0.f;
#pragma unroll
            for (int nn = 0; nn < 4; nn++) {
                const float* xr = sX + (grp * 4 + nn) * 520;
                const float a0 = xr[u];
                const float b0 = xr[128 + u * 3 + 0];
                const float b1 = xr[128 + u * 3 + 1];
                const float b2 = xr[128 + u * 3 + 2];
                a_sc0[nn] = fmaf(a0, ws0, a_sc0[nn]);
                a_u0[nn]  = fmaf(a0, wu0, a_u0[nn]);
                a_dn[nn]  = fmaf(a0, wd,  a_dn[nn]);
                a_sc1[nn][0] = fmaf(b0, ws1, a_sc1[nn][0]);
                a_sc1[nn][1] = fmaf(b1, ws1, a_sc1[nn][1]);
                a_sc1[nn][2] = fmaf(b2, ws1, a_sc1[nn][2]);
                a_u1[nn][0] = fmaf(b0, wu1, a_u1[nn][0]);
                a_u1[nn][1] = fmaf(b1, wu1, a_u1[nn][1]);
                a_u1[nn][2] = fmaf(b2, wu1, a_u1[nn][2]);
            }
        }
    }

#pragma unroll
    for (int nn = 0; nn < 4; nn++) {
        const int n = n0 + grp * 4 + nn;
        out_sc[(size_t)n * 512 + v] = a_sc0[nn] * INV_S128;
        out_sc[(size_t)n * 512 + 128 + v * 3 + 0] = a_sc1[nn][0] * INV_S128;
        out_sc[(size_t)n * 512 + 128 + v * 3 + 1] = a_sc1[nn][1] * INV_S128;
        out_sc[(size_t)n * 512 + 128 + v * 3 + 2] = a_sc1[nn][2] * INV_S128;
        float4 uo = make_float4(a_u0[nn] * INV_S128, a_u1[nn][0] * INV_S128,
                                a_u1[nn][1] * INV_S128, a_u1[nn][2] * INV_S128);
        *(float4*)(&g_u[((size_t)n * 128 + v) * 4]) = uo;
        if (v < 64) g_down[(size_t)n * 64 + v] = a_dn[nn] * INV_S128;
    }
}

// ---------------------------------------------------------------------------
// Kernel 2: fused edge MLP (tf32 mma.sync) + message scatter.
// 64 edges / block, 256 threads = 8 warps; warp w owns cols [w*32, w*32+32).
// ---------------------------------------------------------------------------
#define TE 64
#define LDA 260
#define LDW 264                         // 264 % 32 == 8 -> conflict-free B frags
#define KC 16                           // weight-stage rows (2 k8 chunks)
#define K2_SMEM ((TE * LDA * 2 + KC * LDW + 256 + 128) * 4)

__device__ __forceinline__ void red4(float* p, float4 v) {
    asm volatile("red.global.add.v4.f32 [%0], {%1, %2, %3, %4};"
                 :: "l"(p), "f"(v.x), "f"(v.y), "f"(v.z), "f"(v.w) : "memory");
}

// out[64,256] = silu?( scale * in[64,Kreal] @ W[Kreal, col0:col0+256] )
// sIn holds tf32-bit floats. If store_tf32, sOut gets tf32 bits (feeds next MMA);
// else full fp32 (feeds scatter).
__device__ __forceinline__ void mlp_layer_mma(
    const float* __restrict__ Wg, int ldw, int col0, int Kreal, int Kpad,
    const float* sIn, float* sOut, float* sW,
    float scale, bool act, bool store_tf32)
{
    const int tid  = threadIdx.x;
    const int lane = tid & 31, warp = tid >> 5;
    const int n0   = warp * 32;
    const int g    = lane >> 2, tig = lane & 3;

    float c[4][4][4];
#pragma unroll
    for (int mi = 0; mi < 4; mi++)
#pragma unroll
        for (int ni = 0; ni < 4; ni++)
#pragma unroll
            for (int q = 0; q < 4; q++) c[mi][ni][q] = 0.f;

    for (int k0 = 0; k0 < Kpad; k0 += KC) {
        __syncthreads();
#pragma unroll
        for (int r = 0; r < KC; r++) {
            const int krow = k0 + r;
            const float w = (krow < Kreal) ? Wg[(size_t)krow * ldw + col0 + tid] : 0.f;
            sW[r * LDW + tid] = __uint_as_float(f2tf32(w));
        }
        __syncthreads();
#pragma unroll
        for (int kh = 0; kh < 2; kh++) {
            const int kb = kh * 8;
            unsigned a[4][4], b[4][2];
#pragma unroll
            for (int mi = 0; mi < 4; mi++) {
                const float* ap = sIn + (mi * 16 + g) * LDA + k0 + kb + tig;
                a[mi][0] = __float_as_uint(ap[0]);
                a[mi][1] = __float_as_uint(ap[8 * LDA]);
                a[mi][2] = __float_as_uint(ap[4]);
                a[mi][3] = __float_as_uint(ap[8 * LDA + 4]);
            }
#pragma unroll
            for (int ni = 0; ni < 4; ni++) {
                const float* bp = sW + (kb + tig) * LDW + n0 + ni * 8 + g;
                b[ni][0] = __float_as_uint(bp[0]);
                b[ni][1] = __float_as_uint(bp[4 * LDW]);
            }
#pragma unroll
            for (int mi = 0; mi < 4; mi++)
#pragma unroll
                for (int ni = 0; ni < 4; ni++)
                    mma_tf32(c[mi][ni], a[mi], b[ni]);
        }
    }
    __syncthreads();

    // epilogue: c frag (mi,ni): rows mi*16+g / +8, cols n0+ni*8+tig*2 (+1)
#pragma unroll
    for (int mi = 0; mi < 4; mi++) {
#pragma unroll
        for (int ni = 0; ni < 4; ni++) {
            float v[4];
#pragma unroll
            for (int q = 0; q < 4; q++) {
                float x = c[mi][ni][q] * scale;
                if (act) x = x * (1.0f / (1.0f + __expf(-x)));
                if (store_tf32) x = __uint_as_float(f2tf32(x));
                v[q] = x;
            }
            const int col = n0 + ni * 8 + tig * 2;
            const int r0 = mi * 16 + g;
            *(float2*)(sOut + r0 * LDA + col)            = make_float2(v[0], v[1]);
            *(float2*)(sOut + (r0 + 8) * LDA + col)      = make_float2(v[2], v[3]);
        }
    }
    __syncthreads();
}

__device__ __forceinline__ void scatter_half(
    const float* sTP, const int* sSend, const int* sRecv, const float* sEA, int half)
{
    const int tid = threadIdx.x;
    for (int g = tid; g < TE * 128; g += 256) {
        const int e = g >> 7, c = g & 127;
        const int s = sSend[e], r = sRecv[e];
        const float4 ea = *(const float4*)(sEA + e * 4);   // y0 = ea.x, y1 = ea.y/z/w
        const float4 u = *(const float4*)(&g_u[((size_t)s * 128 + c) * 4]);
        const float* tp = sTP + e * LDA;
        float4 out;
        if (half == 0) {
            const float w0 = tp[c], w1 = tp[128 + c];
            const float t0 = w0 * u.x;
            const float t1 = w1 * u.x;
            out.x = t0 * ea.x;
            out.y = t1 * ea.y; out.z = t1 * ea.z; out.w = t1 * ea.w;
            red4(&g_m[((size_t)r * 256 + c) * 4], out);
        } else {
            const float w2 = tp[c], w3 = tp[128 + c];
            const float dot = u.y * ea.y + u.z * ea.z + u.w * ea.w;
            out.x = w3 * dot * INV_SQRT3;
            out.y = w2 * u.y * ea.x;
            out.z = w2 * u.z * ea.x;
            out.w = w2 * u.w * ea.x;
            red4(&g_m[((size_t)r * 256 + 128 + c) * 4], out);
        }
    }
}

__global__ __launch_bounds__(256, 1) void edge_kernel(
    const float* __restrict__ ef, const float* __restrict__ ea,
    const int* __restrict__ eidx,
    const float* __restrict__ w1, const float* __restrict__ w2,
    const float* __restrict__ w3, const float* __restrict__ w4)
{
    extern __shared__ float sm[];
    float* sA  = sm;                       // 64 x 260
    float* sB  = sA + TE * LDA;            // 64 x 260
    float* sW  = sB + TE * LDA;            // KC x 264
    float* sEA = sW + KC * LDW;            // 64 x 4
    int*  sSend = (int*)(sEA + 256);       // 64
    int*  sRecv = sSend + 64;              // 64

    const int tid = threadIdx.x;
    const int e0 = blockIdx.x * TE;

    if (tid < TE) {
        sSend[tid] = eidx[e0 + tid];
        sRecv[tid] = eidx[EE + e0 + tid];
    }
    sEA[tid] = ea[(size_t)e0 * 4 + tid];   // 256 values
    __syncthreads();

    // aug = [edge_feats(8) | down[s](64) | down[r](64) | zero-pad(8)], tf32 bits
    for (int g = tid; g < TE * 8; g += 256) {
        int e = g >> 3, j = g & 7;
        sA[e * LDA + j] = __uint_as_float(f2tf32(ef[(size_t)(e0 + e) * 8 + j]));
        sA[e * LDA + 136 + j] = 0.f;       // pad cols 136..143
    }
    for (int g = tid; g < TE * 64; g += 256) {
        int e = g >> 6, j = g & 63;
        sA[e * LDA + 8 + j]  = __uint_as_float(f2tf32(g_down[(size_t)sSend[e] * 64 + j]));
        sA[e * LDA + 72 + j] = __uint_as_float(f2tf32(g_down[(size_t)sRecv[e] * 64 + j]));
    }
    __syncthreads();

    mlp_layer_mma(w1, 256, 0,   136, 144, sA, sB, sW, INV_S136, true,  true);
    mlp_layer_mma(w2, 256, 0,   256, 256, sB, sA, sW, INV_S256, true,  true);
    mlp_layer_mma(w3, 256, 0,   256, 256, sA, sB, sW, INV_S256, true,  true);
    mlp_layer_mma(w4, 512, 0,   256, 256, sB, sA, sW, INV_S256, false, false); // {w0,w1}
    scatter_half(sA, sSend, sRecv, sEA, 0);
    __syncthreads();
    mlp_layer_mma(w4, 512, 256, 256, 256, sB, sA, sW, INV_S256, false, false); // {w2,w3}
    scatter_half(sA, sSend, sRecv, sEA, 1);
}

// ---------------------------------------------------------------------------
// Kernel 3: final node GEMM -> message output (unchanged).
// ---------------------------------------------------------------------------
#define K3_SMEM ((8 * 1024 + 2 * 32 * 128) * 4)

__global__ __launch_bounds__(256, 1) void final_kernel(
    const float* __restrict__ Wl0, const float* __restrict__ Wl1,
    float* __restrict__ out_msg)
{
    extern __shared__ float sm[];
    float* sM  = sm;                  // 8 x 1024
    float* sL0 = sM + 8 * 1024;
    float* sL1 = sL0 + 32 * 128;

    const int tid = threadIdx.x;
    const int n0 = blockIdx.x * 8;

    for (int g = tid; g < 8 * 256; g += 256) {
        int nn = g >> 8, q = g & 255;
        ((float4*)(sM + nn * 1024))[q] = ((const float4*)g_m)[(size_t)(n0 + nn) * 256 + q];
    }

    const int v = tid & 127, grp = tid >> 7;
    float acc0[4] = {0,0,0,0};
    float acc1[4][3] = {{0}};

    for (int k0 = 0; k0 < 256; k0 += 32) {
        __syncthreads();
        for (int g = tid; g < 32 * 128; g += 256) {
            int r = g >> 7, c = g & 127;
            sL0[g] = Wl0[(k0 + r) * 128 + c];
            sL1[g] = Wl1[(k0 + r) * 128 + c];
        }
        __syncthreads();
#pragma unroll 4
        for (int uu = 0; uu < 32; uu++) {
            const float w0 = sL0[uu * 128 + v];
            const float w1 = sL1[uu * 128 + v];
#pragma unroll
            for (int nn = 0; nn < 4; nn++) {
                const float4 a = *(const float4*)(sM + (grp * 4 + nn) * 1024 + (k0 + uu) * 4);
                acc0[nn]    = fmaf(a.x, w0, acc0[nn]);
                acc1[nn][0] = fmaf(a.y, w1, acc1[nn][0]);
                acc1[nn][1] = fmaf(a.z, w1, acc1[nn][1]);
                acc1[nn][2] = fmaf(a.w, w1, acc1[nn][2]);
            }
        }
    }

#pragma unroll
    for (int nn = 0; nn < 4; nn++) {
        const int n = n0 + grp * 4 + nn;
        float4 o = make_float4(acc0[nn] * FINAL_SCALE, acc1[nn][0] * FINAL_SCALE,
                               acc1[nn][1] * FINAL_SCALE, acc1[nn][2] * FINAL_SCALE);
        *(float4*)(out_msg + (size_t)n * 512 + v * 4) = o;
    }
}

// ---------------------------------------------------------------------------
extern "C" void kernel_launch(void* const* d_in, const int* in_sizes, int n_in,
                              void* d_out, int out_size)
{
    const float* node_feats = (const float*)d_in[1];
    const float* edge_attrs = (const float*)d_in[2];
    const float* edge_feats = (const float*)d_in[3];
    const int*   edge_index = (const int*)d_in[4];
    const float* W_up0   = (const float*)d_in[5];
    const float* W_up1   = (const float*)d_in[6];
    const float* W_down  = (const float*)d_in[7];
    const float* mlp_w1  = (const float*)d_in[8];
    const float* mlp_w2  = (const float*)d_in[9];
    const float* mlp_w3  = (const float*)d_in[10];
    const float* mlp_w4  = (const float*)d_in[11];
    const float* W_lin0  = (const float*)d_in[12];
    const float* W_lin1  = (const float*)d_in[13];
    const float* W_skip0 = (const float*)d_in[14];
    const float* W_skip1 = (const float*)d_in[15];
    float* out = (float*)d_out;   // [message (N*512) | sc (N*512)]

    cudaFuncSetAttribute(node_kernel,  cudaFuncAttributeMaxDynamicSharedMemorySize, K1_SMEM);
    cudaFuncSetAttribute(edge_kernel,  cudaFuncAttributeMaxDynamicSharedMemorySize, K2_SMEM);
    cudaFuncSetAttribute(final_kernel, cudaFuncAttributeMaxDynamicSharedMemorySize, K3_SMEM);

    zero_m_kernel<<<NN, 256>>>();
    node_kernel<<<NN / 8, 256, K1_SMEM>>>(node_feats, W_skip0, W_skip1,
                                          W_up0, W_up1, W_down,
                                          out + (size_t)NN * 512);
    edge_kernel<<<EE / TE, 256, K2_SMEM>>>(edge_feats, edge_attrs, edge_index,
                                           mlp_w1, mlp_w2, mlp_w3, mlp_w4);
    final_kernel<<<NN / 8, 256, K3_SMEM>>>(W_lin0, W_lin1, out);
}